// round 14
// baseline (speedup 1.0000x reference)
#include <cuda_runtime.h>
#include <cuda_bf16.h>
#include <math.h>
#include <cstdint>

#define BATCH 2
#define SEQ   768
#define DIM   768
#define NH    8
#define HD    96
#define BH    (BATCH*NH)          // 16
#define ROWS  (BATCH*SEQ)         // 1536
#define NOUT  (BATCH*SEQ*DIM)     // 1179648
#define NPROB (BATCH*NH*SEQ*SEQ)  // 9437184
#define WSZ   (DIM*DIM)           // 589824
#define LNEPS 1e-5f

// ---------------- device scratch ----------------
__device__ __align__(256) float g_Q[NOUT];       // tf32-valued fp32
__device__ __align__(256) float g_K[NOUT];       // tf32-valued fp32
__device__ __align__(256) float g_att[NOUT];
__device__ __align__(256) float g_hst[NOUT];     // tf32-rounded hs
__device__ __align__(256) float g_Wqt[WSZ];      // tf32-rounded Wq
__device__ __align__(256) float g_Wkt[WSZ];      // tf32-rounded Wk
__device__ __align__(256) __nv_bfloat16 g_hsh[NOUT];
__device__ __align__(256) __nv_bfloat16 g_Wvh[WSZ];
__device__ __align__(256) __nv_bfloat16 g_Woh[WSZ];
__device__ __align__(256) __nv_bfloat16 g_ctxh[NOUT];
__device__ __align__(256) __nv_bfloat16 g_Pb[NPROB];
__device__ __align__(256) __nv_bfloat16 g_Vt[BATCH*DIM*SEQ + 32*SEQ]; // [b][d][s], guard

// ---------------- helpers ----------------
__device__ __forceinline__ uint32_t smem_u32(const void* p) {
    uint32_t a;
    asm("{ .reg .u64 t; cvta.to.shared.u64 t, %1; cvt.u32.u64 %0, t; }" : "=r"(a) : "l"(p));
    return a;
}
__device__ __forceinline__ void ldm4(uint32_t r[4], uint32_t a) {
    asm volatile("ldmatrix.sync.aligned.m8n8.x4.shared.b16 {%0,%1,%2,%3}, [%4];"
        : "=r"(r[0]), "=r"(r[1]), "=r"(r[2]), "=r"(r[3]) : "r"(a));
}
__device__ __forceinline__ void mma16816(float c[4], const uint32_t a[4], const uint32_t b[2]) {
    asm volatile("mma.sync.aligned.m16n8k16.row.col.f32.bf16.bf16.f32 "
        "{%0,%1,%2,%3}, {%4,%5,%6,%7}, {%8,%9}, {%0,%1,%2,%3};"
        : "+f"(c[0]), "+f"(c[1]), "+f"(c[2]), "+f"(c[3])
        : "r"(a[0]), "r"(a[1]), "r"(a[2]), "r"(a[3]), "r"(b[0]), "r"(b[1]));
}
__device__ __forceinline__ void mma1688tf(float c[4], const uint32_t a[4], const uint32_t b[2]) {
    asm volatile("mma.sync.aligned.m16n8k8.row.col.f32.tf32.tf32.f32 "
        "{%0,%1,%2,%3}, {%4,%5,%6,%7}, {%8,%9}, {%0,%1,%2,%3};"
        : "+f"(c[0]), "+f"(c[1]), "+f"(c[2]), "+f"(c[3])
        : "r"(a[0]), "r"(a[1]), "r"(a[2]), "r"(a[3]), "r"(b[0]), "r"(b[1]));
}
__device__ __forceinline__ float tf32r(float x) {
    uint32_t u;
    asm("cvt.rna.tf32.f32 %0, %1;" : "=r"(u) : "f"(x));
    return __uint_as_float(u);
}
__device__ __forceinline__ void cp16(uint32_t dst, const void* src) {
    asm volatile("cp.async.cg.shared.global [%0], [%1], 16;" :: "r"(dst), "l"(src) : "memory");
}
__device__ __forceinline__ void cp_commit() { asm volatile("cp.async.commit_group;" ::: "memory"); }
template<int N> __device__ __forceinline__ void cp_wait() {
    asm volatile("cp.async.wait_group %0;" :: "n"(N) : "memory");
}

#define SST  40     // bf16 smem row stride (elems)
#define SSTF 36     // fp32 smem row stride (elems)

template<int MT, int NT>
struct TCfg {
    static constexpr int WR = (MT >= 128) ? 2 : 1;
    static constexpr int WC = 4 / WR;
    static constexpr int WM = MT / WR;
    static constexpr int WN = NT / WC;
    static constexpr int FM = WM / 16;
    static constexpr int FN = WN / 8;
};

// ---------------- bf16 engine ----------------
template<int MT, int NT>
__device__ __forceinline__ void gemm_tile_t(
    const __nv_bfloat16* __restrict__ A, int lda,
    const __nv_bfloat16* __restrict__ B, int ldb,
    int m0, int n0, int K,
    float acc[TCfg<MT,NT>::FM][TCfg<MT,NT>::FN][4], char* smem)
{
    using C = TCfg<MT, NT>;
    constexpr int ABY = MT * SST * 2;
    constexpr int STGB = (MT + NT) * SST * 2;
    const int tid = threadIdx.x;
    const int wid = tid >> 5, lane = tid & 31;
    const int wm = wid / C::WC, wn = wid % C::WC;
    const uint32_t s0 = smem_u32(smem);
    const int row = tid >> 2;
    const int jj  = tid & 3;
    const int nch = K / 32;

    auto loadStage = [&](int stage, int k0) {
        uint32_t dA = s0 + stage * STGB;
        uint32_t dB = dA + ABY;
        #pragma unroll
        for (int i = 0; i < MT / 32; ++i) {
            int r = row + i * 32;
            cp16(dA + (r * SST + jj * 8) * 2, A + (size_t)(m0 + r) * lda + k0 + jj * 8);
        }
        #pragma unroll
        for (int i = 0; i < NT / 32; ++i) {
            int r = row + i * 32;
            cp16(dB + (r * SST + jj * 8) * 2, B + (size_t)(n0 + r) * ldb + k0 + jj * 8);
        }
        cp_commit();
    };

    loadStage(0, 0);
    if (nch > 1) loadStage(1, 32);

    int stage = 0;
    for (int c = 0; c < nch; ++c) {
        if (c + 1 < nch) cp_wait<1>(); else cp_wait<0>();
        __syncthreads();
        if (c + 2 < nch) {
            int ns = stage + 2; if (ns >= 3) ns -= 3;
            loadStage(ns, (c + 2) * 32);
        }
        uint32_t bA = s0 + stage * STGB;
        uint32_t bB = bA + ABY;
        #pragma unroll
        for (int ks = 0; ks < 2; ++ks) {
            const int k16 = ks * 16;
            uint32_t af[C::FM][4], bfr[C::FN][2];
            #pragma unroll
            for (int mf = 0; mf < C::FM; ++mf) {
                int baseRow = wm * C::WM + mf * 16;
                int mi = lane >> 3, r = lane & 7;
                int rr = baseRow + (mi & 1) * 8 + r;
                int cc = k16 + (mi >> 1) * 8;
                ldm4(af[mf], bA + (rr * SST + cc) * 2);
            }
            #pragma unroll
            for (int nfp = 0; nfp < C::FN / 2; ++nfp) {
                int baseRow = wn * C::WN + nfp * 16;
                int g = lane >> 3, r = lane & 7;
                int rr = baseRow + (g >> 1) * 8 + r;
                int cc = k16 + (g & 1) * 8;
                uint32_t t[4];
                ldm4(t, bB + (rr * SST + cc) * 2);
                bfr[2 * nfp][0] = t[0]; bfr[2 * nfp][1] = t[1];
                bfr[2 * nfp + 1][0] = t[2]; bfr[2 * nfp + 1][1] = t[3];
            }
            #pragma unroll
            for (int mf = 0; mf < C::FM; ++mf)
                #pragma unroll
                for (int nf = 0; nf < C::FN; ++nf)
                    mma16816(acc[mf][nf], af[mf], bfr[nf]);
        }
        if (++stage == 3) stage = 0;
    }
    __syncthreads();
}

// ---------------- tf32 engine ----------------
template<int MT, int NT>
__device__ __forceinline__ void gemm_tile_tf32(
    const float* __restrict__ A, int lda,
    const float* __restrict__ B, int ldb,
    int m0, int n0, int K,
    float acc[TCfg<MT,NT>::FM][TCfg<MT,NT>::FN][4], char* smem)
{
    using C = TCfg<MT, NT>;
    constexpr int ABY = MT * SSTF * 4;
    constexpr int STGB = (MT + NT) * SSTF * 4;
    const int tid = threadIdx.x;
    const int wid = tid >> 5, lane = tid & 31;
    const int wm = wid / C::WC, wn = wid % C::WC;
    const uint32_t s0 = smem_u32(smem);
    const int row = tid >> 3;   // 0..15
    const int jj  = tid & 7;    // 16B chunk (4 floats)
    const int nch = K / 32;

    auto loadStage = [&](int stage, int k0) {
        uint32_t dA = s0 + stage * STGB;
        uint32_t dB = dA + ABY;
        #pragma unroll
        for (int i = 0; i < MT / 16; ++i) {
            int r = row + i * 16;
            cp16(dA + (r * SSTF + jj * 4) * 4, A + (size_t)(m0 + r) * lda + k0 + jj * 4);
        }
        #pragma unroll
        for (int i = 0; i < NT / 16; ++i) {
            int r = row + i * 16;
            cp16(dB + (r * SSTF + jj * 4) * 4, B + (size_t)(n0 + r) * ldb + k0 + jj * 4);
        }
        cp_commit();
    };

    loadStage(0, 0);
    if (nch > 1) loadStage(1, 32);

    int stage = 0;
    for (int c = 0; c < nch; ++c) {
        if (c + 1 < nch) cp_wait<1>(); else cp_wait<0>();
        __syncthreads();
        if (c + 2 < nch) {
            int ns = stage + 2; if (ns >= 3) ns -= 3;
            loadStage(ns, (c + 2) * 32);
        }
        uint32_t bA = s0 + stage * STGB;
        uint32_t bB = bA + ABY;
        #pragma unroll
        for (int ks = 0; ks < 4; ++ks) {
            const int k8 = ks * 8;
            uint32_t af[C::FM][4], bfr[C::FN][2];
            #pragma unroll
            for (int mf = 0; mf < C::FM; ++mf) {
                int baseRow = wm * C::WM + mf * 16;
                int m = lane >> 3, r = lane & 7;
                int rr = baseRow + (m & 1) * 8 + r;
                int cc = k8 + (m >> 1) * 4;
                ldm4(af[mf], bA + (rr * SSTF + cc) * 4);
            }
            #pragma unroll
            for (int nfp = 0; nfp < C::FN / 2; ++nfp) {
                int baseRow = wn * C::WN + nfp * 16;
                int m = lane >> 3, r = lane & 7;
                int rr = baseRow + (m >> 1) * 8 + r;
                int cc = k8 + (m & 1) * 4;
                uint32_t t[4];
                ldm4(t, bB + (rr * SSTF + cc) * 4);
                bfr[2 * nfp][0] = t[0]; bfr[2 * nfp][1] = t[1];
                bfr[2 * nfp + 1][0] = t[2]; bfr[2 * nfp + 1][1] = t[3];
            }
            #pragma unroll
            for (int mf = 0; mf < C::FM; ++mf)
                #pragma unroll
                for (int nf = 0; nf < C::FN; ++nf)
                    mma1688tf(acc[mf][nf], af[mf], bfr[nf]);
        }
        if (++stage == 3) stage = 0;
    }
    __syncthreads();
}

#define SMEM3T_128   (3*(128+128)*SSTF*4)  // 110592 (tf32 128x128)
#define SMEM3_32128  (3*(32+128)*SST*2)    // 38400  (bf16 32x128)
#define STGB_T128    ((128+128)*SSTF*4)    // 36864  (per-stage bytes, tf32 128x128)

// ---------------- stage 1: Q/K proj (tf32 1-pass) + Vt = Wv @ hs^T (bf16) ----------------
__global__ void __launch_bounds__(128) gemm_stage1(
    const float* __restrict__ bq, const float* __restrict__ bk,
    const float* __restrict__ bv)
{
    const int z = blockIdx.z;
    if (z >= 2 && blockIdx.y >= 6) return;
    extern __shared__ __align__(16) char smem[];
    const int m0 = blockIdx.y << 7, n0 = blockIdx.x << 7;
    const int wid = threadIdx.x >> 5, lane = threadIdx.x & 31;
    const int wm = wid >> 1, wn = wid & 1;
    float acc[4][8][4] = {};

    if (z < 2) {
        const float* B = z ? g_Wkt : g_Wqt;
        gemm_tile_tf32<128,128>(g_hst, DIM, B, DIM, m0, n0, DIM, acc, smem);
        const float* bias = z ? bk : bq;
        float* C = z ? g_K : g_Q;
        #pragma unroll
        for (int mf = 0; mf < 4; ++mf) {
            int r = m0 + wm * 64 + mf * 16 + (lane >> 2);
            #pragma unroll
            for (int nf = 0; nf < 8; ++nf) {
                int c = n0 + wn * 64 + nf * 8 + (lane & 3) * 2;
                float b0 = bias[c], b1 = bias[c + 1];
                float2 v0 = {tf32r(acc[mf][nf][0] + b0), tf32r(acc[mf][nf][1] + b1)};
                float2 v1 = {tf32r(acc[mf][nf][2] + b0), tf32r(acc[mf][nf][3] + b1)};
                *(float2*)(C + (size_t)r * DIM + c) = v0;
                *(float2*)(C + (size_t)(r + 8) * DIM + c) = v1;
            }
        }
    } else {
        const int b = z - 2;
        const __nv_bfloat16* B = g_hsh + (size_t)b * SEQ * DIM;
        gemm_tile_t<128,128>(g_Wvh, DIM, B, DIM, m0, n0, DIM, acc, smem);
        __nv_bfloat16* Vt = g_Vt + (size_t)b * DIM * SEQ;
        #pragma unroll
        for (int mf = 0; mf < 4; ++mf) {
            int r = m0 + wm * 64 + mf * 16 + (lane >> 2);
            float bv0 = bv[r], bv8 = bv[r + 8];
            #pragma unroll
            for (int nf = 0; nf < 8; ++nf) {
                int c = n0 + wn * 64 + nf * 8 + (lane & 3) * 2;
                __nv_bfloat162 h0, h1;
                h0.x = __float2bfloat16(acc[mf][nf][0] + bv0);
                h0.y = __float2bfloat16(acc[mf][nf][1] + bv0);
                h1.x = __float2bfloat16(acc[mf][nf][2] + bv8);
                h1.y = __float2bfloat16(acc[mf][nf][3] + bv8);
                *(__nv_bfloat162*)(Vt + (size_t)r * SEQ + c) = h0;
                *(__nv_bfloat162*)(Vt + (size_t)(r + 8) * SEQ + c) = h1;
            }
        }
    }
}

// ---------------- scores: per-head tf32 Q.K^T (K=96), 128x128 tiles ----------------
__global__ void __launch_bounds__(128) gemm_scores(
    const float* __restrict__ dist, const float* __restrict__ ang,
    const float* __restrict__ mask, float* __restrict__ P,
    const float* __restrict__ Wd, const float* __restrict__ bd,
    const float* __restrict__ Wa, const float* __restrict__ ba)
{
    extern __shared__ __align__(16) char smem[];
    const int z = blockIdx.z, b = z >> 3, h = z & 7;
    const float* A = g_Q + (size_t)b * SEQ * DIM + h * HD;
    const float* B = g_K + (size_t)b * SEQ * DIM + h * HD;
    const int m0 = blockIdx.y << 7, n0 = blockIdx.x << 7;
    float acc[4][8][4] = {};
    gemm_tile_tf32<128,128>(A, DIM, B, DIM, m0, n0, HD, acc, smem);

    const int wid = threadIdx.x >> 5, lane = threadIdx.x & 31;
    const int wm = wid >> 1, wn = wid & 1;
    const float inv = 0.1020620726159657f;  // 1/sqrt(96)

    // ---- in-CTA rank-1 coefficients from smem A-tile ----
    float cd[8] = {}, ca[8] = {}, c0[8] = {};
    {
        const int dl = lane & 3;
        const float* smf = (const float*)smem;
        #pragma unroll 4
        for (int j = 0; j < 24; ++j) {
            int d = dl + j * 4;
            float wd = Wd[d], wa = Wa[d], bb = bd[d] + ba[d];
            int st = d >> 5, dc = d & 31;
            const float* srow = smf + (size_t)st * (STGB_T128 / 4) + dc;
            #pragma unroll
            for (int i = 0; i < 8; ++i) {
                int rl = wm * 64 + (i >> 1) * 16 + (lane >> 2) + (i & 1) * 8;
                float q = srow[rl * SSTF];
                cd[i] = fmaf(q, wd, cd[i]);
                ca[i] = fmaf(q, wa, ca[i]);
                c0[i] = fmaf(q, bb, c0[i]);
            }
        }
        #pragma unroll
        for (int i = 0; i < 8; ++i) {
            cd[i] += __shfl_xor_sync(0xffffffffu, cd[i], 1);
            cd[i] += __shfl_xor_sync(0xffffffffu, cd[i], 2);
            ca[i] += __shfl_xor_sync(0xffffffffu, ca[i], 1);
            ca[i] += __shfl_xor_sync(0xffffffffu, ca[i], 2);
            c0[i] += __shfl_xor_sync(0xffffffffu, c0[i], 1);
            c0[i] += __shfl_xor_sync(0xffffffffu, c0[i], 2);
        }
    }

    float mkb[8][2];
    #pragma unroll
    for (int nf = 0; nf < 8; ++nf) {
        int c = n0 + wn * 64 + nf * 8 + (lane & 3) * 2;
        float2 mk = *(const float2*)(mask + b * SEQ + c);
        mkb[nf][0] = (1.0f - mk.x) * -10000.0f;
        mkb[nf][1] = (1.0f - mk.y) * -10000.0f;
    }

    #pragma unroll
    for (int mf = 0; mf < 4; ++mf) {
        int r0 = m0 + wm * 64 + mf * 16 + (lane >> 2);
        #pragma unroll
        for (int half = 0; half < 2; ++half) {
            int r = r0 + half * 8;
            int i = mf * 2 + half;
            float cdv = cd[i], cav = ca[i], c0v = c0[i];
            const float* drow = dist + ((size_t)b * SEQ + r) * SEQ;
            const float* arow = ang  + ((size_t)b * SEQ + r) * SEQ;
            float* prow = P + ((size_t)z * SEQ + r) * SEQ;
            #pragma unroll
            for (int nf = 0; nf < 8; ++nf) {
                int c = n0 + wn * 64 + nf * 8 + (lane & 3) * 2;
                float2 dv = *(const float2*)(drow + c);
                float2 av = *(const float2*)(arow + c);
                float s0 = acc[mf][nf][half * 2 + 0] * inv;
                float s1 = acc[mf][nf][half * 2 + 1] * inv;
                s0 = fmaf(dv.x, cdv, s0); s0 = fmaf(av.x, cav, s0);
                s1 = fmaf(dv.y, cdv, s1); s1 = fmaf(av.y, cav, s1);
                float2 o;
                o.x = s0 + c0v + mkb[nf][0];
                o.y = s1 + c0v + mkb[nf][1];
                *(float2*)(prow + c) = o;
            }
        }
    }
}

// ---------------- ctx = P @ V^T slice (bf16, 32x128 tiles, 384 CTAs) ----------------
__global__ void __launch_bounds__(128) gemm_ctx()
{
    extern __shared__ __align__(16) char smem[];
    const int z = blockIdx.z, b = z >> 3, h = z & 7;
    const __nv_bfloat16* A = g_Pb + (size_t)z * SEQ * SEQ;
    const __nv_bfloat16* B = g_Vt + (size_t)b * DIM * SEQ;
    const int m0 = blockIdx.y << 5;
    float acc[2][4][4] = {};
    gemm_tile_t<32,128>(A, SEQ, B, SEQ, m0, h * HD, SEQ, acc, smem);

    const int wid = threadIdx.x >> 5, lane = threadIdx.x & 31;
    const int wn = wid & 3;
    if (wn == 3) return;
    #pragma unroll
    for (int mf = 0; mf < 2; ++mf) {
        int r = m0 + mf * 16 + (lane >> 2);
        #pragma unroll
        for (int nf = 0; nf < 4; ++nf) {
            int c = wn * 32 + nf * 8 + (lane & 3) * 2;
            __nv_bfloat162 h0, h1;
            h0.x = __float2bfloat16(acc[mf][nf][0]);
            h0.y = __float2bfloat16(acc[mf][nf][1]);
            h1.x = __float2bfloat16(acc[mf][nf][2]);
            h1.y = __float2bfloat16(acc[mf][nf][3]);
            *(__nv_bfloat162*)(g_ctxh + ((size_t)b * SEQ + r) * DIM + h * HD + c) = h0;
            *(__nv_bfloat162*)(g_ctxh + ((size_t)b * SEQ + r + 8) * DIM + h * HD + c) = h1;
        }
    }
}

// ---------------- out projection (bf16, 32x128 tiles, 288 CTAs) ----------------
__global__ void __launch_bounds__(128) gemm_out(const float* __restrict__ bo)
{
    extern __shared__ __align__(16) char smem[];
    const int m0 = blockIdx.y << 5, n0 = blockIdx.x << 7;
    float acc[2][4][4] = {};
    gemm_tile_t<32,128>(g_ctxh, DIM, g_Woh, DIM, m0, n0, DIM, acc, smem);

    const int wid = threadIdx.x >> 5, lane = threadIdx.x & 31;
    const int wn = wid & 3;
    #pragma unroll
    for (int mf = 0; mf < 2; ++mf) {
        int r = m0 + mf * 16 + (lane >> 2);
        #pragma unroll
        for (int nf = 0; nf < 4; ++nf) {
            int c = n0 + wn * 32 + nf * 8 + (lane & 3) * 2;
            float b0 = bo[c], b1 = bo[c + 1];
            float2 v0 = {acc[mf][nf][0] + b0, acc[mf][nf][1] + b1};
            float2 v1 = {acc[mf][nf][2] + b0, acc[mf][nf][3] + b1};
            *(float2*)(g_att + (size_t)r * DIM + c) = v0;
            *(float2*)(g_att + (size_t)(r + 8) * DIM + c) = v1;
        }
    }
}

// ---------------- batched operand prep ----------------
__global__ void __launch_bounds__(256) prep_all(
    const float* __restrict__ hs, const float* __restrict__ Wq,
    const float* __restrict__ Wk, const float* __restrict__ Wv,
    const float* __restrict__ Wo)
{
    const int z = blockIdx.y;
    const int idx = blockIdx.x * 256 + threadIdx.x;
    const int e = idx * 2;
    if (z == 0) {
        float2 v = *(const float2*)(hs + e);
        float2 t = {tf32r(v.x), tf32r(v.y)};
        *(float2*)(g_hst + e) = t;
        __nv_bfloat162 hh;
        hh.x = __float2bfloat16(v.x); hh.y = __float2bfloat16(v.y);
        *(__nv_bfloat162*)(g_hsh + e) = hh;
        return;
    }
    if (e >= WSZ) return;
    if (z <= 2) {
        const float* w = (z == 1) ? Wq : Wk;
        float* y = (z == 1) ? g_Wqt : g_Wkt;
        float2 v = *(const float2*)(w + e);
        float2 t = {tf32r(v.x), tf32r(v.y)};
        *(float2*)(y + e) = t;
    } else {
        const float* w = (z == 3) ? Wv : Wo;
        __nv_bfloat16* y = (z == 3) ? g_Wvh : g_Woh;
        float2 v = *(const float2*)(w + e);
        __nv_bfloat162 hh;
        hh.x = __float2bfloat16(v.x); hh.y = __float2bfloat16(v.y);
        *(__nv_bfloat162*)(y + e) = hh;
    }
}

// ---------------- reductions ----------------
__device__ __forceinline__ float warp_sum(float v) {
    #pragma unroll
    for (int o = 16; o; o >>= 1) v += __shfl_xor_sync(0xffffffffu, v, o);
    return v;
}
__device__ __forceinline__ float warp_max(float v) {
    #pragma unroll
    for (int o = 16; o; o >>= 1) v = fmaxf(v, __shfl_xor_sync(0xffffffffu, v, o));
    return v;
}

// ---------------- softmax: 2 rows per 384-thread block, float4 per thread ----------------
__global__ void __launch_bounds__(384) softmax_kernel(float* __restrict__ P)
{
    __shared__ float shm[12];
    __shared__ float shs[12];
    const int sub = threadIdx.x / 192;         // row within pair
    const int tid = threadIdx.x % 192;
    const size_t row = (size_t)blockIdx.x * 2 + sub;
    float* p = P + row * SEQ;
    __nv_bfloat16* pb = g_Pb + row * SEQ;
    const int wrp = threadIdx.x >> 5;          // 0..11 (0-5 row0, 6-11 row1)
    const int lane = threadIdx.x & 31;
    const int base = sub * 6;

    float4 v = *(const float4*)(p + tid * 4);

    float mx = fmaxf(fmaxf(v.x, v.y), fmaxf(v.z, v.w));
    mx = warp_max(mx);
    if (lane == 0) shm[wrp] = mx;
    __syncthreads();
    mx = shm[base];
    #pragma unroll
    for (int i = 1; i < 6; ++i) mx = fmaxf(mx, shm[base + i]);

    v.x = __expf(v.x - mx); v.y = __expf(v.y - mx);
    v.z = __expf(v.z - mx); v.w = __expf(v.w - mx);
    float s = (v.x + v.y) + (v.z + v.w);
    s = warp_sum(s);
    if (lane == 0) shs[wrp] = s;
    __syncthreads();
    s = shs[base];
    #pragma unroll
    for (int i = 1; i < 6; ++i) s += shs[base + i];

    float r = 1.0f / s;
    v.x *= r; v.y *= r; v.z *= r; v.w *= r;
    *(float4*)(p + tid * 4) = v;

    __nv_bfloat162 b01, b23;
    b01.x = __float2bfloat16(v.x); b01.y = __float2bfloat16(v.y);
    b23.x = __float2bfloat16(v.z); b23.y = __float2bfloat16(v.w);
    uint2 packed;
    packed.x = *(uint32_t*)&b01;
    packed.y = *(uint32_t*)&b23;
    *(uint2*)(pb + tid * 4) = packed;
}

// ---------------- residual + layernorm (vectorized: 192 threads, float4) ----------------
__global__ void __launch_bounds__(192) ln_kernel(
    const float* __restrict__ hs, const float* __restrict__ lng,
    const float* __restrict__ lnb, float* __restrict__ out)
{
    __shared__ float sh1[6];
    __shared__ float sh2[6];
    const int row = blockIdx.x;
    const int tid = threadIdx.x;
    const int wrp = tid >> 5, lane = tid & 31;
    const int c = tid * 4;

    float4 a  = *(const float4*)(g_att + (size_t)row * DIM + c);
    float4 x0 = *(const float4*)(hs    + (size_t)row * DIM + c);
    float4 x;
    x.x = a.x + x0.x; x.y = a.y + x0.y; x.z = a.z + x0.z; x.w = a.w + x0.w;

    float s  = (x.x + x.y) + (x.z + x.w);
    float s2 = fmaf(x.x, x.x, fmaf(x.y, x.y, fmaf(x.z, x.z, x.w * x.w)));
    s = warp_sum(s); s2 = warp_sum(s2);
    if (lane == 0) { sh1[wrp] = s; sh2[wrp] = s2; }
    __syncthreads();
    s = sh1[0]; s2 = sh2[0];
    #pragma unroll
    for (int i = 1; i < 6; ++i) { s += sh1[i]; s2 += sh2[i]; }

    const float mu = s * (1.0f / DIM);
    const float var = s2 * (1.0f / DIM) - mu * mu;
    const float rs = rsqrtf(var + LNEPS);

    float4 g = *(const float4*)(lng + c);
    float4 bb = *(const float4*)(lnb + c);
    float4 o;
    o.x = (x.x - mu) * rs * g.x + bb.x;
    o.y = (x.y - mu) * rs * g.y + bb.y;
    o.z = (x.z - mu) * rs * g.z + bb.z;
    o.w = (x.w - mu) * rs * g.w + bb.w;
    *(float4*)(out + (size_t)row * DIM + c) = o;
}

// ---------------- launcher ----------------
extern "C" void kernel_launch(void* const* d_in, const int* in_sizes, int n_in,
                              void* d_out, int out_size)
{
    const float* hs   = (const float*)d_in[0];
    const float* dist = (const float*)d_in[1];
    const float* ang  = (const float*)d_in[2];
    const float* mask = (const float*)d_in[3];
    const float* Wq   = (const float*)d_in[4];
    const float* bq   = (const float*)d_in[5];
    const float* Wk   = (const float*)d_in[6];
    const float* bk   = (const float*)d_in[7];
    const float* Wv   = (const float*)d_in[8];
    const float* bv   = (const float*)d_in[9];
    const float* Wd   = (const float*)d_in[10];
    const float* bd   = (const float*)d_in[11];
    const float* Wa   = (const float*)d_in[12];
    const float* ba   = (const float*)d_in[13];
    const float* Wo   = (const float*)d_in[14];
    const float* bo   = (const float*)d_in[15];
    const float* lng  = (const float*)d_in[16];
    const float* lnb  = (const float*)d_in[17];

    float* out   = (float*)d_out;
    float* probs = out + NOUT;

    static bool attr_done = false;
    if (!attr_done) {
        cudaFuncSetAttribute(gemm_stage1, cudaFuncAttributeMaxDynamicSharedMemorySize, SMEM3T_128);
        cudaFuncSetAttribute(gemm_scores, cudaFuncAttributeMaxDynamicSharedMemorySize, SMEM3T_128);
        cudaFuncSetAttribute(gemm_ctx,    cudaFuncAttributeMaxDynamicSharedMemorySize, SMEM3_32128);
        cudaFuncSetAttribute(gemm_out,    cudaFuncAttributeMaxDynamicSharedMemorySize, SMEM3_32128);
        attr_done = true;
    }

    // 1. operand prep
    prep_all<<<dim3(NOUT/512, 5), 256>>>(hs, Wq, Wk, Wv, Wo);

    // 2. stage-1: Q,K proj (tf32) + Vt (bf16, b=0,1)
    gemm_stage1<<<dim3(DIM/128, ROWS/128, 4), 128, SMEM3T_128>>>(bq, bk, bv);

    // 3. scores (tf32, K=96) with fused rank-1 coefficients + bias/mask
    gemm_scores<<<dim3(SEQ/128, SEQ/128, BH), 128, SMEM3T_128>>>(
        dist, ang, mask, probs, Wd, bd, Wa, ba);

    // 4. softmax (2 rows per block)
    softmax_kernel<<<(BH * SEQ) / 2, 384>>>(probs);

    // 5. ctx = P @ V (bf16, 32x128 tiles -> 384 CTAs)
    gemm_ctx<<<dim3(1, SEQ/32, BH), 128, SMEM3_32128>>>();

    // 6. out projection (bf16, 32x128 tiles -> 288 CTAs)
    gemm_out<<<dim3(DIM/128, ROWS/32, 1), 128, SMEM3_32128>>>(bo);

    // 7. residual + LN (vectorized)
    ln_kernel<<<ROWS, 192>>>(hs, lng, lnb, out);
}

// round 15
// speedup vs baseline: 1.0142x; 1.0142x over previous
#include <cuda_runtime.h>
#include <cuda_bf16.h>
#include <math.h>
#include <cstdint>

#define BATCH 2
#define SEQ   768
#define DIM   768
#define NH    8
#define HD    96
#define BH    (BATCH*NH)          // 16
#define ROWS  (BATCH*SEQ)         // 1536
#define NOUT  (BATCH*SEQ*DIM)     // 1179648
#define WSZ   (DIM*DIM)           // 589824
#define LNEPS 1e-5f

// ---------------- device scratch ----------------
__device__ __align__(256) float g_Q[NOUT];       // tf32-valued fp32
__device__ __align__(256) float g_K[NOUT];       // tf32-valued fp32
__device__ __align__(256) float g_att[NOUT];
__device__ __align__(256) float g_hst[NOUT];     // tf32-rounded hs
__device__ __align__(256) float g_Wqt[WSZ];      // tf32-rounded Wq
__device__ __align__(256) float g_Wkt[WSZ];      // tf32-rounded Wk
__device__ __align__(256) __nv_bfloat16 g_hsh[NOUT];
__device__ __align__(256) __nv_bfloat16 g_Wvh[WSZ];
__device__ __align__(256) __nv_bfloat16 g_Woh[WSZ];
__device__ __align__(256) __nv_bfloat16 g_ctxh[NOUT];
__device__ __align__(256) __nv_bfloat16 g_Vt[BATCH*DIM*SEQ + 32*SEQ]; // [b][d][s], guard

// ---------------- helpers ----------------
__device__ __forceinline__ uint32_t smem_u32(const void* p) {
    uint32_t a;
    asm("{ .reg .u64 t; cvta.to.shared.u64 t, %1; cvt.u32.u64 %0, t; }" : "=r"(a) : "l"(p));
    return a;
}
__device__ __forceinline__ void ldm4(uint32_t r[4], uint32_t a) {
    asm volatile("ldmatrix.sync.aligned.m8n8.x4.shared.b16 {%0,%1,%2,%3}, [%4];"
        : "=r"(r[0]), "=r"(r[1]), "=r"(r[2]), "=r"(r[3]) : "r"(a));
}
__device__ __forceinline__ void mma16816(float c[4], const uint32_t a[4], const uint32_t b[2]) {
    asm volatile("mma.sync.aligned.m16n8k16.row.col.f32.bf16.bf16.f32 "
        "{%0,%1,%2,%3}, {%4,%5,%6,%7}, {%8,%9}, {%0,%1,%2,%3};"
        : "+f"(c[0]), "+f"(c[1]), "+f"(c[2]), "+f"(c[3])
        : "r"(a[0]), "r"(a[1]), "r"(a[2]), "r"(a[3]), "r"(b[0]), "r"(b[1]));
}
__device__ __forceinline__ void mma1688tf(float c[4], const uint32_t a[4], const uint32_t b[2]) {
    asm volatile("mma.sync.aligned.m16n8k8.row.col.f32.tf32.tf32.f32 "
        "{%0,%1,%2,%3}, {%4,%5,%6,%7}, {%8,%9}, {%0,%1,%2,%3};"
        : "+f"(c[0]), "+f"(c[1]), "+f"(c[2]), "+f"(c[3])
        : "r"(a[0]), "r"(a[1]), "r"(a[2]), "r"(a[3]), "r"(b[0]), "r"(b[1]));
}
__device__ __forceinline__ float tf32r(float x) {
    uint32_t u;
    asm("cvt.rna.tf32.f32 %0, %1;" : "=r"(u) : "f"(x));
    return __uint_as_float(u);
}
__device__ __forceinline__ void cp16(uint32_t dst, const void* src) {
    asm volatile("cp.async.cg.shared.global [%0], [%1], 16;" :: "r"(dst), "l"(src) : "memory");
}
__device__ __forceinline__ void cp_commit() { asm volatile("cp.async.commit_group;" ::: "memory"); }
template<int N> __device__ __forceinline__ void cp_wait() {
    asm volatile("cp.async.wait_group %0;" :: "n"(N) : "memory");
}

#define SST  40     // bf16 smem row stride (elems)
#define SSTF 36     // fp32 smem row stride (elems)

template<int MT, int NT>
struct TCfg {
    static constexpr int WR = (MT >= 128) ? 2 : 1;
    static constexpr int WC = 4 / WR;
    static constexpr int WM = MT / WR;
    static constexpr int WN = NT / WC;
    static constexpr int FM = WM / 16;
    static constexpr int FN = WN / 8;
};

// ---------------- bf16 engine ----------------
template<int MT, int NT>
__device__ __forceinline__ void gemm_tile_t(
    const __nv_bfloat16* __restrict__ A, int lda,
    const __nv_bfloat16* __restrict__ B, int ldb,
    int m0, int n0, int K,
    float acc[TCfg<MT,NT>::FM][TCfg<MT,NT>::FN][4], char* smem)
{
    using C = TCfg<MT, NT>;
    constexpr int ABY = MT * SST * 2;
    constexpr int STGB = (MT + NT) * SST * 2;
    const int tid = threadIdx.x;
    const int wid = tid >> 5, lane = tid & 31;
    const int wm = wid / C::WC, wn = wid % C::WC;
    const uint32_t s0 = smem_u32(smem);
    const int row = tid >> 2;
    const int jj  = tid & 3;
    const int nch = K / 32;

    auto loadStage = [&](int stage, int k0) {
        uint32_t dA = s0 + stage * STGB;
        uint32_t dB = dA + ABY;
        #pragma unroll
        for (int i = 0; i < MT / 32; ++i) {
            int r = row + i * 32;
            cp16(dA + (r * SST + jj * 8) * 2, A + (size_t)(m0 + r) * lda + k0 + jj * 8);
        }
        #pragma unroll
        for (int i = 0; i < NT / 32; ++i) {
            int r = row + i * 32;
            cp16(dB + (r * SST + jj * 8) * 2, B + (size_t)(n0 + r) * ldb + k0 + jj * 8);
        }
        cp_commit();
    };

    loadStage(0, 0);
    if (nch > 1) loadStage(1, 32);

    int stage = 0;
    for (int c = 0; c < nch; ++c) {
        if (c + 1 < nch) cp_wait<1>(); else cp_wait<0>();
        __syncthreads();
        if (c + 2 < nch) {
            int ns = stage + 2; if (ns >= 3) ns -= 3;
            loadStage(ns, (c + 2) * 32);
        }
        uint32_t bA = s0 + stage * STGB;
        uint32_t bB = bA + ABY;
        #pragma unroll
        for (int ks = 0; ks < 2; ++ks) {
            const int k16 = ks * 16;
            uint32_t af[C::FM][4], bfr[C::FN][2];
            #pragma unroll
            for (int mf = 0; mf < C::FM; ++mf) {
                int baseRow = wm * C::WM + mf * 16;
                int mi = lane >> 3, r = lane & 7;
                int rr = baseRow + (mi & 1) * 8 + r;
                int cc = k16 + (mi >> 1) * 8;
                ldm4(af[mf], bA + (rr * SST + cc) * 2);
            }
            #pragma unroll
            for (int nfp = 0; nfp < C::FN / 2; ++nfp) {
                int baseRow = wn * C::WN + nfp * 16;
                int g = lane >> 3, r = lane & 7;
                int rr = baseRow + (g >> 1) * 8 + r;
                int cc = k16 + (g & 1) * 8;
                uint32_t t[4];
                ldm4(t, bB + (rr * SST + cc) * 2);
                bfr[2 * nfp][0] = t[0]; bfr[2 * nfp][1] = t[1];
                bfr[2 * nfp + 1][0] = t[2]; bfr[2 * nfp + 1][1] = t[3];
            }
            #pragma unroll
            for (int mf = 0; mf < C::FM; ++mf)
                #pragma unroll
                for (int nf = 0; nf < C::FN; ++nf)
                    mma16816(acc[mf][nf], af[mf], bfr[nf]);
        }
        if (++stage == 3) stage = 0;
    }
    __syncthreads();
}

// ---------------- tf32 engine ----------------
template<int MT, int NT>
__device__ __forceinline__ void gemm_tile_tf32(
    const float* __restrict__ A, int lda,
    const float* __restrict__ B, int ldb,
    int m0, int n0, int K,
    float acc[TCfg<MT,NT>::FM][TCfg<MT,NT>::FN][4], char* smem)
{
    using C = TCfg<MT, NT>;
    constexpr int ABY = MT * SSTF * 4;
    constexpr int STGB = (MT + NT) * SSTF * 4;
    const int tid = threadIdx.x;
    const int wid = tid >> 5, lane = tid & 31;
    const int wm = wid / C::WC, wn = wid % C::WC;
    const uint32_t s0 = smem_u32(smem);
    const int row = tid >> 3;   // 0..15
    const int jj  = tid & 7;    // 16B chunk (4 floats)
    const int nch = K / 32;

    auto loadStage = [&](int stage, int k0) {
        uint32_t dA = s0 + stage * STGB;
        uint32_t dB = dA + ABY;
        #pragma unroll
        for (int i = 0; i < MT / 16; ++i) {
            int r = row + i * 16;
            cp16(dA + (r * SSTF + jj * 4) * 4, A + (size_t)(m0 + r) * lda + k0 + jj * 4);
        }
        #pragma unroll
        for (int i = 0; i < NT / 16; ++i) {
            int r = row + i * 16;
            cp16(dB + (r * SSTF + jj * 4) * 4, B + (size_t)(n0 + r) * ldb + k0 + jj * 4);
        }
        cp_commit();
    };

    loadStage(0, 0);
    if (nch > 1) loadStage(1, 32);

    int stage = 0;
    for (int c = 0; c < nch; ++c) {
        if (c + 1 < nch) cp_wait<1>(); else cp_wait<0>();
        __syncthreads();
        if (c + 2 < nch) {
            int ns = stage + 2; if (ns >= 3) ns -= 3;
            loadStage(ns, (c + 2) * 32);
        }
        uint32_t bA = s0 + stage * STGB;
        uint32_t bB = bA + ABY;
        #pragma unroll
        for (int ks = 0; ks < 4; ++ks) {
            const int k8 = ks * 8;
            uint32_t af[C::FM][4], bfr[C::FN][2];
            #pragma unroll
            for (int mf = 0; mf < C::FM; ++mf) {
                int baseRow = wm * C::WM + mf * 16;
                int m = lane >> 3, r = lane & 7;
                int rr = baseRow + (m & 1) * 8 + r;
                int cc = k8 + (m >> 1) * 4;
                ldm4(af[mf], bA + (rr * SSTF + cc) * 4);
            }
            #pragma unroll
            for (int nfp = 0; nfp < C::FN / 2; ++nfp) {
                int baseRow = wn * C::WN + nfp * 16;
                int m = lane >> 3, r = lane & 7;
                int rr = baseRow + (m >> 1) * 8 + r;
                int cc = k8 + (m & 1) * 4;
                uint32_t t[4];
                ldm4(t, bB + (rr * SSTF + cc) * 4);
                bfr[2 * nfp][0] = t[0]; bfr[2 * nfp][1] = t[1];
                bfr[2 * nfp + 1][0] = t[2]; bfr[2 * nfp + 1][1] = t[3];
            }
            #pragma unroll
            for (int mf = 0; mf < C::FM; ++mf)
                #pragma unroll
                for (int nf = 0; nf < C::FN; ++nf)
                    mma1688tf(acc[mf][nf], af[mf], bfr[nf]);
        }
        if (++stage == 3) stage = 0;
    }
    __syncthreads();
}

#define SMEM3T_128   (3*(128+128)*SSTF*4)  // 110592 (tf32 128x128)
#define SMEM3_64128  (3*(64+128)*SST*2)    // 46080  (bf16 64x128)
#define STGB_T128    ((128+128)*SSTF*4)    // 36864
#define ASTRIDE      776                   // persistent A smem stride (bf16 elems)
#define CTX_ABYTES   (32*ASTRIDE*2)        // 49664
#define CTX_BSTG     (128*SST*2)           // 10240 per stage
#define SMEM_CTXF    (CTX_ABYTES + 3*CTX_BSTG)  // 80384

// ---------------- stage 1: Q/K proj (tf32 1-pass) + Vt = Wv @ hs^T (bf16) ----------------
__global__ void __launch_bounds__(128) gemm_stage1(
    const float* __restrict__ bq, const float* __restrict__ bk,
    const float* __restrict__ bv)
{
    const int z = blockIdx.z;
    if (z >= 2 && blockIdx.y >= 6) return;
    extern __shared__ __align__(16) char smem[];
    const int m0 = blockIdx.y << 7, n0 = blockIdx.x << 7;
    const int wid = threadIdx.x >> 5, lane = threadIdx.x & 31;
    const int wm = wid >> 1, wn = wid & 1;
    float acc[4][8][4] = {};

    if (z < 2) {
        const float* B = z ? g_Wkt : g_Wqt;
        gemm_tile_tf32<128,128>(g_hst, DIM, B, DIM, m0, n0, DIM, acc, smem);
        const float* bias = z ? bk : bq;
        float* C = z ? g_K : g_Q;
        #pragma unroll
        for (int mf = 0; mf < 4; ++mf) {
            int r = m0 + wm * 64 + mf * 16 + (lane >> 2);
            #pragma unroll
            for (int nf = 0; nf < 8; ++nf) {
                int c = n0 + wn * 64 + nf * 8 + (lane & 3) * 2;
                float b0 = bias[c], b1 = bias[c + 1];
                float2 v0 = {tf32r(acc[mf][nf][0] + b0), tf32r(acc[mf][nf][1] + b1)};
                float2 v1 = {tf32r(acc[mf][nf][2] + b0), tf32r(acc[mf][nf][3] + b1)};
                *(float2*)(C + (size_t)r * DIM + c) = v0;
                *(float2*)(C + (size_t)(r + 8) * DIM + c) = v1;
            }
        }
    } else {
        const int b = z - 2;
        const __nv_bfloat16* B = g_hsh + (size_t)b * SEQ * DIM;
        gemm_tile_t<128,128>(g_Wvh, DIM, B, DIM, m0, n0, DIM, acc, smem);
        __nv_bfloat16* Vt = g_Vt + (size_t)b * DIM * SEQ;
        #pragma unroll
        for (int mf = 0; mf < 4; ++mf) {
            int r = m0 + wm * 64 + mf * 16 + (lane >> 2);
            float bv0 = bv[r], bv8 = bv[r + 8];
            #pragma unroll
            for (int nf = 0; nf < 8; ++nf) {
                int c = n0 + wn * 64 + nf * 8 + (lane & 3) * 2;
                __nv_bfloat162 h0, h1;
                h0.x = __float2bfloat16(acc[mf][nf][0] + bv0);
                h0.y = __float2bfloat16(acc[mf][nf][1] + bv0);
                h1.x = __float2bfloat16(acc[mf][nf][2] + bv8);
                h1.y = __float2bfloat16(acc[mf][nf][3] + bv8);
                *(__nv_bfloat162*)(Vt + (size_t)r * SEQ + c) = h0;
                *(__nv_bfloat162*)(Vt + (size_t)(r + 8) * SEQ + c) = h1;
            }
        }
    }
}

// ---------------- scores: per-head tf32 Q.K^T (K=96), 128x128 tiles ----------------
__global__ void __launch_bounds__(128) gemm_scores(
    const float* __restrict__ dist, const float* __restrict__ ang,
    const float* __restrict__ mask, float* __restrict__ P,
    const float* __restrict__ Wd, const float* __restrict__ bd,
    const float* __restrict__ Wa, const float* __restrict__ ba)
{
    extern __shared__ __align__(16) char smem[];
    const int z = blockIdx.z, b = z >> 3, h = z & 7;
    const float* A = g_Q + (size_t)b * SEQ * DIM + h * HD;
    const float* B = g_K + (size_t)b * SEQ * DIM + h * HD;
    const int m0 = blockIdx.y << 7, n0 = blockIdx.x << 7;
    float acc[4][8][4] = {};
    gemm_tile_tf32<128,128>(A, DIM, B, DIM, m0, n0, HD, acc, smem);

    const int wid = threadIdx.x >> 5, lane = threadIdx.x & 31;
    const int wm = wid >> 1, wn = wid & 1;
    const float inv = 0.1020620726159657f;  // 1/sqrt(96)

    // ---- in-CTA rank-1 coefficients from smem A-tile ----
    float cd[8] = {}, ca[8] = {}, c0[8] = {};
    {
        const int dl = lane & 3;
        const float* smf = (const float*)smem;
        #pragma unroll 4
        for (int j = 0; j < 24; ++j) {
            int d = dl + j * 4;
            float wd = Wd[d], wa = Wa[d], bb = bd[d] + ba[d];
            int st = d >> 5, dc = d & 31;
            const float* srow = smf + (size_t)st * (STGB_T128 / 4) + dc;
            #pragma unroll
            for (int i = 0; i < 8; ++i) {
                int rl = wm * 64 + (i >> 1) * 16 + (lane >> 2) + (i & 1) * 8;
                float q = srow[rl * SSTF];
                cd[i] = fmaf(q, wd, cd[i]);
                ca[i] = fmaf(q, wa, ca[i]);
                c0[i] = fmaf(q, bb, c0[i]);
            }
        }
        #pragma unroll
        for (int i = 0; i < 8; ++i) {
            cd[i] += __shfl_xor_sync(0xffffffffu, cd[i], 1);
            cd[i] += __shfl_xor_sync(0xffffffffu, cd[i], 2);
            ca[i] += __shfl_xor_sync(0xffffffffu, ca[i], 1);
            ca[i] += __shfl_xor_sync(0xffffffffu, ca[i], 2);
            c0[i] += __shfl_xor_sync(0xffffffffu, c0[i], 1);
            c0[i] += __shfl_xor_sync(0xffffffffu, c0[i], 2);
        }
    }

    float mkb[8][2];
    #pragma unroll
    for (int nf = 0; nf < 8; ++nf) {
        int c = n0 + wn * 64 + nf * 8 + (lane & 3) * 2;
        float2 mk = *(const float2*)(mask + b * SEQ + c);
        mkb[nf][0] = (1.0f - mk.x) * -10000.0f;
        mkb[nf][1] = (1.0f - mk.y) * -10000.0f;
    }

    #pragma unroll
    for (int mf = 0; mf < 4; ++mf) {
        int r0 = m0 + wm * 64 + mf * 16 + (lane >> 2);
        #pragma unroll
        for (int half = 0; half < 2; ++half) {
            int r = r0 + half * 8;
            int i = mf * 2 + half;
            float cdv = cd[i], cav = ca[i], c0v = c0[i];
            const float* drow = dist + ((size_t)b * SEQ + r) * SEQ;
            const float* arow = ang  + ((size_t)b * SEQ + r) * SEQ;
            float* prow = P + ((size_t)z * SEQ + r) * SEQ;
            #pragma unroll
            for (int nf = 0; nf < 8; ++nf) {
                int c = n0 + wn * 64 + nf * 8 + (lane & 3) * 2;
                float2 dv = *(const float2*)(drow + c);
                float2 av = *(const float2*)(arow + c);
                float s0 = acc[mf][nf][half * 2 + 0] * inv;
                float s1 = acc[mf][nf][half * 2 + 1] * inv;
                s0 = fmaf(dv.x, cdv, s0); s0 = fmaf(av.x, cav, s0);
                s1 = fmaf(dv.y, cdv, s1); s1 = fmaf(av.y, cav, s1);
                float2 o;
                o.x = s0 + c0v + mkb[nf][0];
                o.y = s1 + c0v + mkb[nf][1];
                *(float2*)(prow + c) = o;
            }
        }
    }
}

// ---------------- fused softmax + ctx: 32 rows per CTA, A in persistent smem ----------------
__global__ void __launch_bounds__(128) gemm_ctx_fused(float* __restrict__ P)
{
    extern __shared__ __align__(16) char smem[];
    __nv_bfloat16* As = (__nv_bfloat16*)smem;           // 32 x ASTRIDE
    char* bstg = smem + CTX_ABYTES;                     // 3 B stages
    const int z = blockIdx.z, b = z >> 3, h = z & 7;
    const int m0 = blockIdx.y << 5;
    const int n0 = h * HD;
    const __nv_bfloat16* B = g_Vt + (size_t)b * DIM * SEQ;
    const int tid = threadIdx.x;
    const int wid = tid >> 5, lane = tid & 31;
    const uint32_t sA = smem_u32(As);
    const uint32_t sB = smem_u32(bstg);
    const int lrow = tid >> 2;    // 0..31 (B loader)
    const int jj   = tid & 3;

    auto loadStageB = [&](int stage, int k0) {
        uint32_t dB = sB + stage * CTX_BSTG;
        #pragma unroll
        for (int i = 0; i < 4; ++i) {
            int r = lrow + i * 32;
            cp16(dB + (r * SST + jj * 8) * 2, B + (size_t)(n0 + r) * SEQ + k0 + jj * 8);
        }
        cp_commit();
    };

    // kick off B pipeline before the softmax prologue (overlaps)
    loadStageB(0, 0);
    loadStageB(1, 32);

    // ---- softmax prologue: warp w handles rows w*8 .. w*8+7 ----
    {
        #pragma unroll 1
        for (int rr8 = 0; rr8 < 8; ++rr8) {
            int rl = wid * 8 + rr8;
            float* prow = P + ((size_t)z * SEQ + m0 + rl) * SEQ;
            float4 v[6];
            #pragma unroll
            for (int i = 0; i < 6; ++i)
                v[i] = *(const float4*)(prow + i * 128 + lane * 4);
            float mx = -1e30f;
            #pragma unroll
            for (int i = 0; i < 6; ++i)
                mx = fmaxf(mx, fmaxf(fmaxf(v[i].x, v[i].y), fmaxf(v[i].z, v[i].w)));
            #pragma unroll
            for (int o = 16; o; o >>= 1) mx = fmaxf(mx, __shfl_xor_sync(0xffffffffu, mx, o));
            float s = 0.f;
            #pragma unroll
            for (int i = 0; i < 6; ++i) {
                v[i].x = __expf(v[i].x - mx); v[i].y = __expf(v[i].y - mx);
                v[i].z = __expf(v[i].z - mx); v[i].w = __expf(v[i].w - mx);
                s += (v[i].x + v[i].y) + (v[i].z + v[i].w);
            }
            #pragma unroll
            for (int o = 16; o; o >>= 1) s += __shfl_xor_sync(0xffffffffu, s, o);
            float rinv = 1.0f / s;
            #pragma unroll
            for (int i = 0; i < 6; ++i) {
                v[i].x *= rinv; v[i].y *= rinv; v[i].z *= rinv; v[i].w *= rinv;
                *(float4*)(prow + i * 128 + lane * 4) = v[i];
                __nv_bfloat162 b01, b23;
                b01.x = __float2bfloat16(v[i].x); b01.y = __float2bfloat16(v[i].y);
                b23.x = __float2bfloat16(v[i].z); b23.y = __float2bfloat16(v[i].w);
                uint2 pk;
                pk.x = *(uint32_t*)&b01;
                pk.y = *(uint32_t*)&b23;
                *(uint2*)(As + rl * ASTRIDE + i * 128 + lane * 4) = pk;
            }
        }
    }

    // ---- mainloop: A from persistent smem, B pipelined ----
    const int wn = wid & 3;                 // 1x4 warps, warp tile 32x32
    float acc[2][4][4] = {};
    int stage = 0;
    const int nch = SEQ / 32;               // 24
    for (int c = 0; c < nch; ++c) {
        if (c + 1 < nch) cp_wait<1>(); else cp_wait<0>();
        __syncthreads();                     // also makes prologue A writes visible (c==0)
        if (c + 2 < nch) {
            int ns = stage + 2; if (ns >= 3) ns -= 3;
            loadStageB(ns, (c + 2) * 32);
        }
        uint32_t bB = sB + stage * CTX_BSTG;
        #pragma unroll
        for (int ks = 0; ks < 2; ++ks) {
            const int k16 = ks * 16;
            uint32_t af[2][4], bfr[4][2];
            #pragma unroll
            for (int mf = 0; mf < 2; ++mf) {
                int baseRow = mf * 16;
                int mi = lane >> 3, r = lane & 7;
                int rr = baseRow + (mi & 1) * 8 + r;
                int ccg = c * 32 + k16 + (mi >> 1) * 8;
                ldm4(af[mf], sA + (rr * ASTRIDE + ccg) * 2);
            }
            #pragma unroll
            for (int nfp = 0; nfp < 2; ++nfp) {
                int baseRow = wn * 32 + nfp * 16;
                int g = lane >> 3, r = lane & 7;
                int rr = baseRow + (g >> 1) * 8 + r;
                int cc = k16 + (g & 1) * 8;
                uint32_t t[4];
                ldm4(t, bB + (rr * SST + cc) * 2);
                bfr[2 * nfp][0] = t[0]; bfr[2 * nfp][1] = t[1];
                bfr[2 * nfp + 1][0] = t[2]; bfr[2 * nfp + 1][1] = t[3];
            }
            #pragma unroll
            for (int mf = 0; mf < 2; ++mf)
                #pragma unroll
                for (int nf = 0; nf < 4; ++nf)
                    mma16816(acc[mf][nf], af[mf], bfr[nf]);
        }
        if (++stage == 3) stage = 0;
    }

    if (wn == 3) return;   // cols 96..127 cross into next head
    #pragma unroll
    for (int mf = 0; mf < 2; ++mf) {
        int r = m0 + mf * 16 + (lane >> 2);
        #pragma unroll
        for (int nf = 0; nf < 4; ++nf) {
            int c = wn * 32 + nf * 8 + (lane & 3) * 2;
            __nv_bfloat162 h0, h1;
            h0.x = __float2bfloat16(acc[mf][nf][0]);
            h0.y = __float2bfloat16(acc[mf][nf][1]);
            h1.x = __float2bfloat16(acc[mf][nf][2]);
            h1.y = __float2bfloat16(acc[mf][nf][3]);
            *(__nv_bfloat162*)(g_ctxh + ((size_t)b * SEQ + r) * DIM + h * HD + c) = h0;
            *(__nv_bfloat162*)(g_ctxh + ((size_t)b * SEQ + r + 8) * DIM + h * HD + c) = h1;
        }
    }
}

// ---------------- out projection (bf16, 64x128 tiles) ----------------
__global__ void __launch_bounds__(128) gemm_out(const float* __restrict__ bo)
{
    extern __shared__ __align__(16) char smem[];
    const int m0 = blockIdx.y << 6, n0 = blockIdx.x << 7;
    float acc[4][4][4] = {};
    gemm_tile_t<64,128>(g_ctxh, DIM, g_Woh, DIM, m0, n0, DIM, acc, smem);

    const int wid = threadIdx.x >> 5, lane = threadIdx.x & 31;
    const int wn = wid & 3;
    #pragma unroll
    for (int mf = 0; mf < 4; ++mf) {
        int r = m0 + mf * 16 + (lane >> 2);
        #pragma unroll
        for (int nf = 0; nf < 4; ++nf) {
            int c = n0 + wn * 32 + nf * 8 + (lane & 3) * 2;
            float b0 = bo[c], b1 = bo[c + 1];
            float2 v0 = {acc[mf][nf][0] + b0, acc[mf][nf][1] + b1};
            float2 v1 = {acc[mf][nf][2] + b0, acc[mf][nf][3] + b1};
            *(float2*)(g_att + (size_t)r * DIM + c) = v0;
            *(float2*)(g_att + (size_t)(r + 8) * DIM + c) = v1;
        }
    }
}

// ---------------- batched operand prep ----------------
__global__ void __launch_bounds__(256) prep_all(
    const float* __restrict__ hs, const float* __restrict__ Wq,
    const float* __restrict__ Wk, const float* __restrict__ Wv,
    const float* __restrict__ Wo)
{
    const int z = blockIdx.y;
    const int idx = blockIdx.x * 256 + threadIdx.x;
    const int e = idx * 2;
    if (z == 0) {
        float2 v = *(const float2*)(hs + e);
        float2 t = {tf32r(v.x), tf32r(v.y)};
        *(float2*)(g_hst + e) = t;
        __nv_bfloat162 hh;
        hh.x = __float2bfloat16(v.x); hh.y = __float2bfloat16(v.y);
        *(__nv_bfloat162*)(g_hsh + e) = hh;
        return;
    }
    if (e >= WSZ) return;
    if (z <= 2) {
        const float* w = (z == 1) ? Wq : Wk;
        float* y = (z == 1) ? g_Wqt : g_Wkt;
        float2 v = *(const float2*)(w + e);
        float2 t = {tf32r(v.x), tf32r(v.y)};
        *(float2*)(y + e) = t;
    } else {
        const float* w = (z == 3) ? Wv : Wo;
        __nv_bfloat16* y = (z == 3) ? g_Wvh : g_Woh;
        float2 v = *(const float2*)(w + e);
        __nv_bfloat162 hh;
        hh.x = __float2bfloat16(v.x); hh.y = __float2bfloat16(v.y);
        *(__nv_bfloat162*)(y + e) = hh;
    }
}

// ---------------- reductions ----------------
__device__ __forceinline__ float warp_sum(float v) {
    #pragma unroll
    for (int o = 16; o; o >>= 1) v += __shfl_xor_sync(0xffffffffu, v, o);
    return v;
}

// ---------------- residual + layernorm (vectorized: 192 threads, float4) ----------------
__global__ void __launch_bounds__(192) ln_kernel(
    const float* __restrict__ hs, const float* __restrict__ lng,
    const float* __restrict__ lnb, float* __restrict__ out)
{
    __shared__ float sh1[6];
    __shared__ float sh2[6];
    const int row = blockIdx.x;
    const int tid = threadIdx.x;
    const int wrp = tid >> 5, lane = tid & 31;
    const int c = tid * 4;

    float4 a  = *(const float4*)(g_att + (size_t)row * DIM + c);
    float4 x0 = *(const float4*)(hs    + (size_t)row * DIM + c);
    float4 x;
    x.x = a.x + x0.x; x.y = a.y + x0.y; x.z = a.z + x0.z; x.w = a.w + x0.w;

    float s  = (x.x + x.y) + (x.z + x.w);
    float s2 = fmaf(x.x, x.x, fmaf(x.y, x.y, fmaf(x.z, x.z, x.w * x.w)));
    s = warp_sum(s); s2 = warp_sum(s2);
    if (lane == 0) { sh1[wrp] = s; sh2[wrp] = s2; }
    __syncthreads();
    s = sh1[0]; s2 = sh2[0];
    #pragma unroll
    for (int i = 1; i < 6; ++i) { s += sh1[i]; s2 += sh2[i]; }

    const float mu = s * (1.0f / DIM);
    const float var = s2 * (1.0f / DIM) - mu * mu;
    const float rs = rsqrtf(var + LNEPS);

    float4 g = *(const float4*)(lng + c);
    float4 bb = *(const float4*)(lnb + c);
    float4 o;
    o.x = (x.x - mu) * rs * g.x + bb.x;
    o.y = (x.y - mu) * rs * g.y + bb.y;
    o.z = (x.z - mu) * rs * g.z + bb.z;
    o.w = (x.w - mu) * rs * g.w + bb.w;
    *(float4*)(out + (size_t)row * DIM + c) = o;
}

// ---------------- launcher ----------------
extern "C" void kernel_launch(void* const* d_in, const int* in_sizes, int n_in,
                              void* d_out, int out_size)
{
    const float* hs   = (const float*)d_in[0];
    const float* dist = (const float*)d_in[1];
    const float* ang  = (const float*)d_in[2];
    const float* mask = (const float*)d_in[3];
    const float* Wq   = (const float*)d_in[4];
    const float* bq   = (const float*)d_in[5];
    const float* Wk   = (const float*)d_in[6];
    const float* bk   = (const float*)d_in[7];
    const float* Wv   = (const float*)d_in[8];
    const float* bv   = (const float*)d_in[9];
    const float* Wd   = (const float*)d_in[10];
    const float* bd   = (const float*)d_in[11];
    const float* Wa   = (const float*)d_in[12];
    const float* ba   = (const float*)d_in[13];
    const float* Wo   = (const float*)d_in[14];
    const float* bo   = (const float*)d_in[15];
    const float* lng  = (const float*)d_in[16];
    const float* lnb  = (const float*)d_in[17];

    float* out   = (float*)d_out;
    float* probs = out + NOUT;

    static bool attr_done = false;
    if (!attr_done) {
        cudaFuncSetAttribute(gemm_stage1,    cudaFuncAttributeMaxDynamicSharedMemorySize, SMEM3T_128);
        cudaFuncSetAttribute(gemm_scores,    cudaFuncAttributeMaxDynamicSharedMemorySize, SMEM3T_128);
        cudaFuncSetAttribute(gemm_ctx_fused, cudaFuncAttributeMaxDynamicSharedMemorySize, SMEM_CTXF);
        cudaFuncSetAttribute(gemm_out,       cudaFuncAttributeMaxDynamicSharedMemorySize, SMEM3_64128);
        attr_done = true;
    }

    // 1. operand prep
    prep_all<<<dim3(NOUT/512, 5), 256>>>(hs, Wq, Wk, Wv, Wo);

    // 2. stage-1: Q,K proj (tf32) + Vt (bf16, b=0,1)
    gemm_stage1<<<dim3(DIM/128, ROWS/128, 4), 128, SMEM3T_128>>>(bq, bk, bv);

    // 3. scores (tf32, K=96) with fused rank-1 coefficients + bias/mask
    gemm_scores<<<dim3(SEQ/128, SEQ/128, BH), 128, SMEM3T_128>>>(
        dist, ang, mask, probs, Wd, bd, Wa, ba);

    // 4. fused softmax + ctx (32 rows per CTA, 384 CTAs)
    gemm_ctx_fused<<<dim3(1, SEQ/32, BH), 128, SMEM_CTXF>>>(probs);

    // 5. out projection (bf16, 64x128 tiles)
    gemm_out<<<dim3(DIM/128, ROWS/64, 1), 128, SMEM3_64128>>>(bo);

    // 6. residual + LN (vectorized)
    ln_kernel<<<ROWS, 192>>>(hs, lng, lnb, out);
}

// round 16
// speedup vs baseline: 1.0455x; 1.0309x over previous
#include <cuda_runtime.h>
#include <cuda_bf16.h>
#include <math.h>
#include <cstdint>

#define BATCH 2
#define SEQ   768
#define DIM   768
#define NH    8
#define HD    96
#define BH    (BATCH*NH)          // 16
#define ROWS  (BATCH*SEQ)         // 1536
#define NOUT  (BATCH*SEQ*DIM)     // 1179648
#define WSZ   (DIM*DIM)           // 589824
#define LNEPS 1e-5f

// ---------------- device scratch ----------------
__device__ __align__(256) float g_Q[NOUT];       // tf32-valued fp32
__device__ __align__(256) float g_K[NOUT];       // tf32-valued fp32
__device__ __align__(256) float g_att[NOUT];
__device__ __align__(256) float g_hst[NOUT];     // tf32-rounded hs
__device__ __align__(256) float g_Wqt[WSZ];      // tf32-rounded Wq
__device__ __align__(256) float g_Wkt[WSZ];      // tf32-rounded Wk
__device__ __align__(256) __nv_bfloat16 g_hsh[NOUT];
__device__ __align__(256) __nv_bfloat16 g_Wvh[WSZ];
__device__ __align__(256) __nv_bfloat16 g_Woh[WSZ];
__device__ __align__(256) __nv_bfloat16 g_ctxh[NOUT];
__device__ __align__(256) __nv_bfloat16 g_Vt[BATCH*DIM*SEQ + 32*SEQ]; // [b][d][s], guard

// ---------------- helpers ----------------
__device__ __forceinline__ uint32_t smem_u32(const void* p) {
    uint32_t a;
    asm("{ .reg .u64 t; cvta.to.shared.u64 t, %1; cvt.u32.u64 %0, t; }" : "=r"(a) : "l"(p));
    return a;
}
__device__ __forceinline__ void ldm4(uint32_t r[4], uint32_t a) {
    asm volatile("ldmatrix.sync.aligned.m8n8.x4.shared.b16 {%0,%1,%2,%3}, [%4];"
        : "=r"(r[0]), "=r"(r[1]), "=r"(r[2]), "=r"(r[3]) : "r"(a));
}
__device__ __forceinline__ void mma16816(float c[4], const uint32_t a[4], const uint32_t b[2]) {
    asm volatile("mma.sync.aligned.m16n8k16.row.col.f32.bf16.bf16.f32 "
        "{%0,%1,%2,%3}, {%4,%5,%6,%7}, {%8,%9}, {%0,%1,%2,%3};"
        : "+f"(c[0]), "+f"(c[1]), "+f"(c[2]), "+f"(c[3])
        : "r"(a[0]), "r"(a[1]), "r"(a[2]), "r"(a[3]), "r"(b[0]), "r"(b[1]));
}
__device__ __forceinline__ void mma1688tf(float c[4], const uint32_t a[4], const uint32_t b[2]) {
    asm volatile("mma.sync.aligned.m16n8k8.row.col.f32.tf32.tf32.f32 "
        "{%0,%1,%2,%3}, {%4,%5,%6,%7}, {%8,%9}, {%0,%1,%2,%3};"
        : "+f"(c[0]), "+f"(c[1]), "+f"(c[2]), "+f"(c[3])
        : "r"(a[0]), "r"(a[1]), "r"(a[2]), "r"(a[3]), "r"(b[0]), "r"(b[1]));
}
__device__ __forceinline__ float tf32r(float x) {
    uint32_t u;
    asm("cvt.rna.tf32.f32 %0, %1;" : "=r"(u) : "f"(x));
    return __uint_as_float(u);
}
__device__ __forceinline__ void cp16(uint32_t dst, const void* src) {
    asm volatile("cp.async.cg.shared.global [%0], [%1], 16;" :: "r"(dst), "l"(src) : "memory");
}
__device__ __forceinline__ void cp_commit() { asm volatile("cp.async.commit_group;" ::: "memory"); }
template<int N> __device__ __forceinline__ void cp_wait() {
    asm volatile("cp.async.wait_group %0;" :: "n"(N) : "memory");
}

#define SST  40     // bf16 smem row stride (elems)
#define SSTF 36     // fp32 smem row stride (elems)

template<int MT, int NT>
struct TCfg {
    static constexpr int WR = (MT >= 128) ? 2 : 1;
    static constexpr int WC = 4 / WR;
    static constexpr int WM = MT / WR;
    static constexpr int WN = NT / WC;
    static constexpr int FM = WM / 16;
    static constexpr int FN = WN / 8;
};

// ---------------- bf16 engine ----------------
template<int MT, int NT>
__device__ __forceinline__ void gemm_tile_t(
    const __nv_bfloat16* __restrict__ A, int lda,
    const __nv_bfloat16* __restrict__ B, int ldb,
    int m0, int n0, int K,
    float acc[TCfg<MT,NT>::FM][TCfg<MT,NT>::FN][4], char* smem)
{
    using C = TCfg<MT, NT>;
    constexpr int ABY = MT * SST * 2;
    constexpr int STGB = (MT + NT) * SST * 2;
    const int tid = threadIdx.x;
    const int wid = tid >> 5, lane = tid & 31;
    const int wm = wid / C::WC, wn = wid % C::WC;
    const uint32_t s0 = smem_u32(smem);
    const int row = tid >> 2;
    const int jj  = tid & 3;
    const int nch = K / 32;

    auto loadStage = [&](int stage, int k0) {
        uint32_t dA = s0 + stage * STGB;
        uint32_t dB = dA + ABY;
        #pragma unroll
        for (int i = 0; i < MT / 32; ++i) {
            int r = row + i * 32;
            cp16(dA + (r * SST + jj * 8) * 2, A + (size_t)(m0 + r) * lda + k0 + jj * 8);
        }
        #pragma unroll
        for (int i = 0; i < NT / 32; ++i) {
            int r = row + i * 32;
            cp16(dB + (r * SST + jj * 8) * 2, B + (size_t)(n0 + r) * ldb + k0 + jj * 8);
        }
        cp_commit();
    };

    loadStage(0, 0);
    if (nch > 1) loadStage(1, 32);

    int stage = 0;
    for (int c = 0; c < nch; ++c) {
        if (c + 1 < nch) cp_wait<1>(); else cp_wait<0>();
        __syncthreads();
        if (c + 2 < nch) {
            int ns = stage + 2; if (ns >= 3) ns -= 3;
            loadStage(ns, (c + 2) * 32);
        }
        uint32_t bA = s0 + stage * STGB;
        uint32_t bB = bA + ABY;
        #pragma unroll
        for (int ks = 0; ks < 2; ++ks) {
            const int k16 = ks * 16;
            uint32_t af[C::FM][4], bfr[C::FN][2];
            #pragma unroll
            for (int mf = 0; mf < C::FM; ++mf) {
                int baseRow = wm * C::WM + mf * 16;
                int mi = lane >> 3, r = lane & 7;
                int rr = baseRow + (mi & 1) * 8 + r;
                int cc = k16 + (mi >> 1) * 8;
                ldm4(af[mf], bA + (rr * SST + cc) * 2);
            }
            #pragma unroll
            for (int nfp = 0; nfp < C::FN / 2; ++nfp) {
                int baseRow = wn * C::WN + nfp * 16;
                int g = lane >> 3, r = lane & 7;
                int rr = baseRow + (g >> 1) * 8 + r;
                int cc = k16 + (g & 1) * 8;
                uint32_t t[4];
                ldm4(t, bB + (rr * SST + cc) * 2);
                bfr[2 * nfp][0] = t[0]; bfr[2 * nfp][1] = t[1];
                bfr[2 * nfp + 1][0] = t[2]; bfr[2 * nfp + 1][1] = t[3];
            }
            #pragma unroll
            for (int mf = 0; mf < C::FM; ++mf)
                #pragma unroll
                for (int nf = 0; nf < C::FN; ++nf)
                    mma16816(acc[mf][nf], af[mf], bfr[nf]);
        }
        if (++stage == 3) stage = 0;
    }
    __syncthreads();
}

// ---------------- tf32 engine ----------------
template<int MT, int NT>
__device__ __forceinline__ void gemm_tile_tf32(
    const float* __restrict__ A, int lda,
    const float* __restrict__ B, int ldb,
    int m0, int n0, int K,
    float acc[TCfg<MT,NT>::FM][TCfg<MT,NT>::FN][4], char* smem)
{
    using C = TCfg<MT, NT>;
    constexpr int ABY = MT * SSTF * 4;
    constexpr int STGB = (MT + NT) * SSTF * 4;
    const int tid = threadIdx.x;
    const int wid = tid >> 5, lane = tid & 31;
    const int wm = wid / C::WC, wn = wid % C::WC;
    const uint32_t s0 = smem_u32(smem);
    const int row = tid >> 3;   // 0..15
    const int jj  = tid & 7;    // 16B chunk (4 floats)
    const int nch = K / 32;

    auto loadStage = [&](int stage, int k0) {
        uint32_t dA = s0 + stage * STGB;
        uint32_t dB = dA + ABY;
        #pragma unroll
        for (int i = 0; i < MT / 16; ++i) {
            int r = row + i * 16;
            cp16(dA + (r * SSTF + jj * 4) * 4, A + (size_t)(m0 + r) * lda + k0 + jj * 4);
        }
        #pragma unroll
        for (int i = 0; i < NT / 16; ++i) {
            int r = row + i * 16;
            cp16(dB + (r * SSTF + jj * 4) * 4, B + (size_t)(n0 + r) * ldb + k0 + jj * 4);
        }
        cp_commit();
    };

    loadStage(0, 0);
    if (nch > 1) loadStage(1, 32);

    int stage = 0;
    for (int c = 0; c < nch; ++c) {
        if (c + 1 < nch) cp_wait<1>(); else cp_wait<0>();
        __syncthreads();
        if (c + 2 < nch) {
            int ns = stage + 2; if (ns >= 3) ns -= 3;
            loadStage(ns, (c + 2) * 32);
        }
        uint32_t bA = s0 + stage * STGB;
        uint32_t bB = bA + ABY;
        #pragma unroll
        for (int ks = 0; ks < 4; ++ks) {
            const int k8 = ks * 8;
            uint32_t af[C::FM][4], bfr[C::FN][2];
            #pragma unroll
            for (int mf = 0; mf < C::FM; ++mf) {
                int baseRow = wm * C::WM + mf * 16;
                int m = lane >> 3, r = lane & 7;
                int rr = baseRow + (m & 1) * 8 + r;
                int cc = k8 + (m >> 1) * 4;
                ldm4(af[mf], bA + (rr * SSTF + cc) * 4);
            }
            #pragma unroll
            for (int nfp = 0; nfp < C::FN / 2; ++nfp) {
                int baseRow = wn * C::WN + nfp * 16;
                int m = lane >> 3, r = lane & 7;
                int rr = baseRow + (m >> 1) * 8 + r;
                int cc = k8 + (m & 1) * 4;
                uint32_t t[4];
                ldm4(t, bB + (rr * SSTF + cc) * 4);
                bfr[2 * nfp][0] = t[0]; bfr[2 * nfp][1] = t[1];
                bfr[2 * nfp + 1][0] = t[2]; bfr[2 * nfp + 1][1] = t[3];
            }
            #pragma unroll
            for (int mf = 0; mf < C::FM; ++mf)
                #pragma unroll
                for (int nf = 0; nf < C::FN; ++nf)
                    mma1688tf(acc[mf][nf], af[mf], bfr[nf]);
        }
        if (++stage == 3) stage = 0;
    }
    __syncthreads();
}

#define SMEM3T_128   (3*(128+128)*SSTF*4)  // 110592 (tf32 128x128)
#define SMEM3_64128  (3*(64+128)*SST*2)    // 46080  (bf16 64x128)
#define STGB_T128    ((128+128)*SSTF*4)    // 36864
#define ASTRIDE      776                   // persistent A smem stride (bf16 elems)
#define CTX_ABYTES   (32*ASTRIDE*2)        // 49664
#define CTX_BSTG     (128*SST*2)           // 10240 per stage
#define SMEM_CTXF    (CTX_ABYTES + 3*CTX_BSTG)  // 80384

// ---------------- stage 1: Q/K proj (tf32 1-pass) + Vt = Wv @ hs^T (bf16) ----------------
__global__ void __launch_bounds__(128) gemm_stage1(
    const float* __restrict__ bq, const float* __restrict__ bk,
    const float* __restrict__ bv)
{
    const int z = blockIdx.z;
    if (z >= 2 && blockIdx.y >= 6) return;
    extern __shared__ __align__(16) char smem[];
    const int m0 = blockIdx.y << 7, n0 = blockIdx.x << 7;
    const int wid = threadIdx.x >> 5, lane = threadIdx.x & 31;
    const int wm = wid >> 1, wn = wid & 1;
    float acc[4][8][4] = {};

    if (z < 2) {
        const float* B = z ? g_Wkt : g_Wqt;
        gemm_tile_tf32<128,128>(g_hst, DIM, B, DIM, m0, n0, DIM, acc, smem);
        const float* bias = z ? bk : bq;
        float* C = z ? g_K : g_Q;
        #pragma unroll
        for (int mf = 0; mf < 4; ++mf) {
            int r = m0 + wm * 64 + mf * 16 + (lane >> 2);
            #pragma unroll
            for (int nf = 0; nf < 8; ++nf) {
                int c = n0 + wn * 64 + nf * 8 + (lane & 3) * 2;
                float b0 = bias[c], b1 = bias[c + 1];
                float2 v0 = {tf32r(acc[mf][nf][0] + b0), tf32r(acc[mf][nf][1] + b1)};
                float2 v1 = {tf32r(acc[mf][nf][2] + b0), tf32r(acc[mf][nf][3] + b1)};
                *(float2*)(C + (size_t)r * DIM + c) = v0;
                *(float2*)(C + (size_t)(r + 8) * DIM + c) = v1;
            }
        }
    } else {
        const int b = z - 2;
        const __nv_bfloat16* B = g_hsh + (size_t)b * SEQ * DIM;
        gemm_tile_t<128,128>(g_Wvh, DIM, B, DIM, m0, n0, DIM, acc, smem);
        __nv_bfloat16* Vt = g_Vt + (size_t)b * DIM * SEQ;
        #pragma unroll
        for (int mf = 0; mf < 4; ++mf) {
            int r = m0 + wm * 64 + mf * 16 + (lane >> 2);
            float bv0 = bv[r], bv8 = bv[r + 8];
            #pragma unroll
            for (int nf = 0; nf < 8; ++nf) {
                int c = n0 + wn * 64 + nf * 8 + (lane & 3) * 2;
                __nv_bfloat162 h0, h1;
                h0.x = __float2bfloat16(acc[mf][nf][0] + bv0);
                h0.y = __float2bfloat16(acc[mf][nf][1] + bv0);
                h1.x = __float2bfloat16(acc[mf][nf][2] + bv8);
                h1.y = __float2bfloat16(acc[mf][nf][3] + bv8);
                *(__nv_bfloat162*)(Vt + (size_t)r * SEQ + c) = h0;
                *(__nv_bfloat162*)(Vt + (size_t)(r + 8) * SEQ + c) = h1;
            }
        }
    }
}

// ---------------- scores: per-head tf32 Q.K^T (K=96), 128x128 tiles ----------------
__global__ void __launch_bounds__(128) gemm_scores(
    const float* __restrict__ dist, const float* __restrict__ ang,
    const float* __restrict__ mask, float* __restrict__ P,
    const float* __restrict__ Wd, const float* __restrict__ bd,
    const float* __restrict__ Wa, const float* __restrict__ ba)
{
    extern __shared__ __align__(16) char smem[];
    const int z = blockIdx.z, b = z >> 3, h = z & 7;
    const float* A = g_Q + (size_t)b * SEQ * DIM + h * HD;
    const float* B = g_K + (size_t)b * SEQ * DIM + h * HD;
    const int m0 = blockIdx.y << 7, n0 = blockIdx.x << 7;
    float acc[4][8][4] = {};
    gemm_tile_tf32<128,128>(A, DIM, B, DIM, m0, n0, HD, acc, smem);

    const int wid = threadIdx.x >> 5, lane = threadIdx.x & 31;
    const int wm = wid >> 1, wn = wid & 1;
    const float inv = 0.1020620726159657f;  // 1/sqrt(96)

    // ---- in-CTA rank-1 coefficients from smem A-tile ----
    float cd[8] = {}, ca[8] = {}, c0[8] = {};
    {
        const int dl = lane & 3;
        const float* smf = (const float*)smem;
        #pragma unroll 4
        for (int j = 0; j < 24; ++j) {
            int d = dl + j * 4;
            float wd = Wd[d], wa = Wa[d], bb = bd[d] + ba[d];
            int st = d >> 5, dc = d & 31;
            const float* srow = smf + (size_t)st * (STGB_T128 / 4) + dc;
            #pragma unroll
            for (int i = 0; i < 8; ++i) {
                int rl = wm * 64 + (i >> 1) * 16 + (lane >> 2) + (i & 1) * 8;
                float q = srow[rl * SSTF];
                cd[i] = fmaf(q, wd, cd[i]);
                ca[i] = fmaf(q, wa, ca[i]);
                c0[i] = fmaf(q, bb, c0[i]);
            }
        }
        #pragma unroll
        for (int i = 0; i < 8; ++i) {
            cd[i] += __shfl_xor_sync(0xffffffffu, cd[i], 1);
            cd[i] += __shfl_xor_sync(0xffffffffu, cd[i], 2);
            ca[i] += __shfl_xor_sync(0xffffffffu, ca[i], 1);
            ca[i] += __shfl_xor_sync(0xffffffffu, ca[i], 2);
            c0[i] += __shfl_xor_sync(0xffffffffu, c0[i], 1);
            c0[i] += __shfl_xor_sync(0xffffffffu, c0[i], 2);
        }
    }

    float mkb[8][2];
    #pragma unroll
    for (int nf = 0; nf < 8; ++nf) {
        int c = n0 + wn * 64 + nf * 8 + (lane & 3) * 2;
        float2 mk = *(const float2*)(mask + b * SEQ + c);
        mkb[nf][0] = (1.0f - mk.x) * -10000.0f;
        mkb[nf][1] = (1.0f - mk.y) * -10000.0f;
    }

    #pragma unroll
    for (int mf = 0; mf < 4; ++mf) {
        int r0 = m0 + wm * 64 + mf * 16 + (lane >> 2);
        #pragma unroll
        for (int half = 0; half < 2; ++half) {
            int r = r0 + half * 8;
            int i = mf * 2 + half;
            float cdv = cd[i], cav = ca[i], c0v = c0[i];
            const float* drow = dist + ((size_t)b * SEQ + r) * SEQ;
            const float* arow = ang  + ((size_t)b * SEQ + r) * SEQ;
            float* prow = P + ((size_t)z * SEQ + r) * SEQ;
            #pragma unroll
            for (int nf = 0; nf < 8; ++nf) {
                int c = n0 + wn * 64 + nf * 8 + (lane & 3) * 2;
                float2 dv = *(const float2*)(drow + c);
                float2 av = *(const float2*)(arow + c);
                float s0 = acc[mf][nf][half * 2 + 0] * inv;
                float s1 = acc[mf][nf][half * 2 + 1] * inv;
                s0 = fmaf(dv.x, cdv, s0); s0 = fmaf(av.x, cav, s0);
                s1 = fmaf(dv.y, cdv, s1); s1 = fmaf(av.y, cav, s1);
                float2 o;
                o.x = s0 + c0v + mkb[nf][0];
                o.y = s1 + c0v + mkb[nf][1];
                *(float2*)(prow + c) = o;
            }
        }
    }
}

// ---------------- fused softmax + ctx: 32 rows per CTA, 256 threads (8 warps) ----------------
__global__ void __launch_bounds__(256) gemm_ctx_fused(float* __restrict__ P)
{
    extern __shared__ __align__(16) char smem[];
    __nv_bfloat16* As = (__nv_bfloat16*)smem;           // 32 x ASTRIDE
    char* bstg = smem + CTX_ABYTES;                     // 3 B stages
    const int z = blockIdx.z, b = z >> 3, h = z & 7;
    const int m0 = blockIdx.y << 5;
    const int n0 = h * HD;
    const __nv_bfloat16* B = g_Vt + (size_t)b * DIM * SEQ;
    const int tid = threadIdx.x;
    const int wid = tid >> 5, lane = tid & 31;          // wid 0..7
    const uint32_t sA = smem_u32(As);
    const uint32_t sB = smem_u32(bstg);
    const int lrow = tid >> 2;    // 0..63 (B loader)
    const int jj   = tid & 3;

    auto loadStageB = [&](int stage, int k0) {
        uint32_t dB = sB + stage * CTX_BSTG;
        #pragma unroll
        for (int i = 0; i < 2; ++i) {
            int r = lrow + i * 64;
            cp16(dB + (r * SST + jj * 8) * 2, B + (size_t)(n0 + r) * SEQ + k0 + jj * 8);
        }
        cp_commit();
    };

    // kick off B pipeline before the softmax prologue (overlaps)
    loadStageB(0, 0);
    loadStageB(1, 32);

    // ---- softmax prologue: warp w handles rows w*4 .. w*4+3 ----
    {
        #pragma unroll 1
        for (int rr4 = 0; rr4 < 4; ++rr4) {
            int rl = wid * 4 + rr4;
            float* prow = P + ((size_t)z * SEQ + m0 + rl) * SEQ;
            float4 v[6];
            #pragma unroll
            for (int i = 0; i < 6; ++i)
                v[i] = *(const float4*)(prow + i * 128 + lane * 4);
            float mx = -1e30f;
            #pragma unroll
            for (int i = 0; i < 6; ++i)
                mx = fmaxf(mx, fmaxf(fmaxf(v[i].x, v[i].y), fmaxf(v[i].z, v[i].w)));
            #pragma unroll
            for (int o = 16; o; o >>= 1) mx = fmaxf(mx, __shfl_xor_sync(0xffffffffu, mx, o));
            float s = 0.f;
            #pragma unroll
            for (int i = 0; i < 6; ++i) {
                v[i].x = __expf(v[i].x - mx); v[i].y = __expf(v[i].y - mx);
                v[i].z = __expf(v[i].z - mx); v[i].w = __expf(v[i].w - mx);
                s += (v[i].x + v[i].y) + (v[i].z + v[i].w);
            }
            #pragma unroll
            for (int o = 16; o; o >>= 1) s += __shfl_xor_sync(0xffffffffu, s, o);
            float rinv = 1.0f / s;
            #pragma unroll
            for (int i = 0; i < 6; ++i) {
                v[i].x *= rinv; v[i].y *= rinv; v[i].z *= rinv; v[i].w *= rinv;
                *(float4*)(prow + i * 128 + lane * 4) = v[i];
                __nv_bfloat162 b01, b23;
                b01.x = __float2bfloat16(v[i].x); b01.y = __float2bfloat16(v[i].y);
                b23.x = __float2bfloat16(v[i].z); b23.y = __float2bfloat16(v[i].w);
                uint2 pk;
                pk.x = *(uint32_t*)&b01;
                pk.y = *(uint32_t*)&b23;
                *(uint2*)(As + rl * ASTRIDE + i * 128 + lane * 4) = pk;
            }
        }
    }

    // ---- mainloop: 8 warps (2m x 4n), warp tile 16x32; A from persistent smem ----
    const int wm = wid >> 2, wn = wid & 3;
    float acc[4][4] = {};
    int stage = 0;
    const int nch = SEQ / 32;               // 24
    for (int c = 0; c < nch; ++c) {
        if (c + 1 < nch) cp_wait<1>(); else cp_wait<0>();
        __syncthreads();                     // also makes prologue A writes visible (c==0)
        if (c + 2 < nch) {
            int ns = stage + 2; if (ns >= 3) ns -= 3;
            loadStageB(ns, (c + 2) * 32);
        }
        uint32_t bB = sB + stage * CTX_BSTG;
        #pragma unroll
        for (int ks = 0; ks < 2; ++ks) {
            const int k16 = ks * 16;
            uint32_t af[4], bfr[4][2];
            {
                int baseRow = wm * 16;
                int mi = lane >> 3, r = lane & 7;
                int rr = baseRow + (mi & 1) * 8 + r;
                int ccg = c * 32 + k16 + (mi >> 1) * 8;
                ldm4(af, sA + (rr * ASTRIDE + ccg) * 2);
            }
            #pragma unroll
            for (int nfp = 0; nfp < 2; ++nfp) {
                int baseRow = wn * 32 + nfp * 16;
                int g = lane >> 3, r = lane & 7;
                int rr = baseRow + (g >> 1) * 8 + r;
                int cc = k16 + (g & 1) * 8;
                uint32_t t[4];
                ldm4(t, bB + (rr * SST + cc) * 2);
                bfr[2 * nfp][0] = t[0]; bfr[2 * nfp][1] = t[1];
                bfr[2 * nfp + 1][0] = t[2]; bfr[2 * nfp + 1][1] = t[3];
            }
            #pragma unroll
            for (int nf = 0; nf < 4; ++nf)
                mma16816(acc[nf], af, bfr[nf]);
        }
        if (++stage == 3) stage = 0;
    }

    if (wn == 3) return;   // cols 96..127 cross into next head
    {
        int r = m0 + wm * 16 + (lane >> 2);
        #pragma unroll
        for (int nf = 0; nf < 4; ++nf) {
            int c = wn * 32 + nf * 8 + (lane & 3) * 2;
            __nv_bfloat162 h0, h1;
            h0.x = __float2bfloat16(acc[nf][0]);
            h0.y = __float2bfloat16(acc[nf][1]);
            h1.x = __float2bfloat16(acc[nf][2]);
            h1.y = __float2bfloat16(acc[nf][3]);
            *(__nv_bfloat162*)(g_ctxh + ((size_t)b * SEQ + r) * DIM + h * HD + c) = h0;
            *(__nv_bfloat162*)(g_ctxh + ((size_t)b * SEQ + r + 8) * DIM + h * HD + c) = h1;
        }
    }
}

// ---------------- out projection (bf16, 64x128 tiles) ----------------
__global__ void __launch_bounds__(128) gemm_out(const float* __restrict__ bo)
{
    extern __shared__ __align__(16) char smem[];
    const int m0 = blockIdx.y << 6, n0 = blockIdx.x << 7;
    float acc[4][4][4] = {};
    gemm_tile_t<64,128>(g_ctxh, DIM, g_Woh, DIM, m0, n0, DIM, acc, smem);

    const int wid = threadIdx.x >> 5, lane = threadIdx.x & 31;
    const int wn = wid & 3;
    #pragma unroll
    for (int mf = 0; mf < 4; ++mf) {
        int r = m0 + mf * 16 + (lane >> 2);
        #pragma unroll
        for (int nf = 0; nf < 4; ++nf) {
            int c = n0 + wn * 32 + nf * 8 + (lane & 3) * 2;
            float b0 = bo[c], b1 = bo[c + 1];
            float2 v0 = {acc[mf][nf][0] + b0, acc[mf][nf][1] + b1};
            float2 v1 = {acc[mf][nf][2] + b0, acc[mf][nf][3] + b1};
            *(float2*)(g_att + (size_t)r * DIM + c) = v0;
            *(float2*)(g_att + (size_t)(r + 8) * DIM + c) = v1;
        }
    }
}

// ---------------- batched operand prep ----------------
__global__ void __launch_bounds__(256) prep_all(
    const float* __restrict__ hs, const float* __restrict__ Wq,
    const float* __restrict__ Wk, const float* __restrict__ Wv,
    const float* __restrict__ Wo)
{
    const int z = blockIdx.y;
    const int idx = blockIdx.x * 256 + threadIdx.x;
    const int e = idx * 2;
    if (z == 0) {
        float2 v = *(const float2*)(hs + e);
        float2 t = {tf32r(v.x), tf32r(v.y)};
        *(float2*)(g_hst + e) = t;
        __nv_bfloat162 hh;
        hh.x = __float2bfloat16(v.x); hh.y = __float2bfloat16(v.y);
        *(__nv_bfloat162*)(g_hsh + e) = hh;
        return;
    }
    if (e >= WSZ) return;
    if (z <= 2) {
        const float* w = (z == 1) ? Wq : Wk;
        float* y = (z == 1) ? g_Wqt : g_Wkt;
        float2 v = *(const float2*)(w + e);
        float2 t = {tf32r(v.x), tf32r(v.y)};
        *(float2*)(y + e) = t;
    } else {
        const float* w = (z == 3) ? Wv : Wo;
        __nv_bfloat16* y = (z == 3) ? g_Wvh : g_Woh;
        float2 v = *(const float2*)(w + e);
        __nv_bfloat162 hh;
        hh.x = __float2bfloat16(v.x); hh.y = __float2bfloat16(v.y);
        *(__nv_bfloat162*)(y + e) = hh;
    }
}

// ---------------- reductions ----------------
__device__ __forceinline__ float warp_sum(float v) {
    #pragma unroll
    for (int o = 16; o; o >>= 1) v += __shfl_xor_sync(0xffffffffu, v, o);
    return v;
}

// ---------------- residual + layernorm (vectorized: 192 threads, float4) ----------------
__global__ void __launch_bounds__(192) ln_kernel(
    const float* __restrict__ hs, const float* __restrict__ lng,
    const float* __restrict__ lnb, float* __restrict__ out)
{
    __shared__ float sh1[6];
    __shared__ float sh2[6];
    const int row = blockIdx.x;
    const int tid = threadIdx.x;
    const int wrp = tid >> 5, lane = tid & 31;
    const int c = tid * 4;

    float4 a  = *(const float4*)(g_att + (size_t)row * DIM + c);
    float4 x0 = *(const float4*)(hs    + (size_t)row * DIM + c);
    float4 x;
    x.x = a.x + x0.x; x.y = a.y + x0.y; x.z = a.z + x0.z; x.w = a.w + x0.w;

    float s  = (x.x + x.y) + (x.z + x.w);
    float s2 = fmaf(x.x, x.x, fmaf(x.y, x.y, fmaf(x.z, x.z, x.w * x.w)));
    s = warp_sum(s); s2 = warp_sum(s2);
    if (lane == 0) { sh1[wrp] = s; sh2[wrp] = s2; }
    __syncthreads();
    s = sh1[0]; s2 = sh2[0];
    #pragma unroll
    for (int i = 1; i < 6; ++i) { s += sh1[i]; s2 += sh2[i]; }

    const float mu = s * (1.0f / DIM);
    const float var = s2 * (1.0f / DIM) - mu * mu;
    const float rs = rsqrtf(var + LNEPS);

    float4 g = *(const float4*)(lng + c);
    float4 bb = *(const float4*)(lnb + c);
    float4 o;
    o.x = (x.x - mu) * rs * g.x + bb.x;
    o.y = (x.y - mu) * rs * g.y + bb.y;
    o.z = (x.z - mu) * rs * g.z + bb.z;
    o.w = (x.w - mu) * rs * g.w + bb.w;
    *(float4*)(out + (size_t)row * DIM + c) = o;
}

// ---------------- launcher ----------------
extern "C" void kernel_launch(void* const* d_in, const int* in_sizes, int n_in,
                              void* d_out, int out_size)
{
    const float* hs   = (const float*)d_in[0];
    const float* dist = (const float*)d_in[1];
    const float* ang  = (const float*)d_in[2];
    const float* mask = (const float*)d_in[3];
    const float* Wq   = (const float*)d_in[4];
    const float* bq   = (const float*)d_in[5];
    const float* Wk   = (const float*)d_in[6];
    const float* bk   = (const float*)d_in[7];
    const float* Wv   = (const float*)d_in[8];
    const float* bv   = (const float*)d_in[9];
    const float* Wd   = (const float*)d_in[10];
    const float* bd   = (const float*)d_in[11];
    const float* Wa   = (const float*)d_in[12];
    const float* ba   = (const float*)d_in[13];
    const float* Wo   = (const float*)d_in[14];
    const float* bo   = (const float*)d_in[15];
    const float* lng  = (const float*)d_in[16];
    const float* lnb  = (const float*)d_in[17];

    float* out   = (float*)d_out;
    float* probs = out + NOUT;

    static bool attr_done = false;
    if (!attr_done) {
        cudaFuncSetAttribute(gemm_stage1,    cudaFuncAttributeMaxDynamicSharedMemorySize, SMEM3T_128);
        cudaFuncSetAttribute(gemm_scores,    cudaFuncAttributeMaxDynamicSharedMemorySize, SMEM3T_128);
        cudaFuncSetAttribute(gemm_ctx_fused, cudaFuncAttributeMaxDynamicSharedMemorySize, SMEM_CTXF);
        cudaFuncSetAttribute(gemm_out,       cudaFuncAttributeMaxDynamicSharedMemorySize, SMEM3_64128);
        attr_done = true;
    }

    // 1. operand prep
    prep_all<<<dim3(NOUT/512, 5), 256>>>(hs, Wq, Wk, Wv, Wo);

    // 2. stage-1: Q,K proj (tf32) + Vt (bf16, b=0,1)
    gemm_stage1<<<dim3(DIM/128, ROWS/128, 4), 128, SMEM3T_128>>>(bq, bk, bv);

    // 3. scores (tf32, K=96) with fused rank-1 coefficients + bias/mask
    gemm_scores<<<dim3(SEQ/128, SEQ/128, BH), 128, SMEM3T_128>>>(
        dist, ang, mask, probs, Wd, bd, Wa, ba);

    // 4. fused softmax + ctx (32 rows per CTA, 256 threads, 384 CTAs)
    gemm_ctx_fused<<<dim3(1, SEQ/32, BH), 256, SMEM_CTXF>>>(probs);

    // 5. out projection (bf16, 64x128 tiles)
    gemm_out<<<dim3(DIM/128, ROWS/64, 1), 128, SMEM3_64128>>>(bo);

    // 6. residual + LN (vectorized)
    ln_kernel<<<ROWS, 192>>>(hs, lng, lnb, out);
}